// round 12
// baseline (speedup 1.0000x reference)
#include <cuda_runtime.h>
#include <cuda_fp16.h>
#include <mma.h>
#include <math.h>
using namespace nvcuda;

#define Sdim 1024
#define Bdim 8
#define Edim 512
#define Hdim 8
#define Ddim 64
#define Ndim 64   // B*H
#define SD 65536  // Sdim*Ddim

// ---------------- scratch ----------------
__device__ __half g_q_h[(size_t)Ndim*Sdim*Ddim];       // [n][s][d] fp16 8MB
__device__ __half g_k_h[(size_t)Ndim*Sdim*Ddim];
__device__ __half g_v_h[(size_t)Ndim*Sdim*Ddim];
__device__ __half g_bias_h[(size_t)Sdim*Sdim*Ndim];    // [j][i][n] fp16 128MB
__device__ __half g_biasT[(size_t)Ndim*Sdim*Sdim];     // [n][i][j] fp16 (mask folded) 128MB
__device__ __half g_attn_h[(size_t)Ndim*Sdim*Sdim];    // probs fp16 [n][i][j] 128MB
__device__ float  g_ctx[(size_t)Sdim*Bdim*Edim];       // [i][n*64+d]
__device__ float  g_x[(size_t)Sdim*Bdim*Edim];

typedef wmma::fragment<wmma::matrix_a,16,16,8,wmma::precision::tf32,wmma::row_major> FragA;
typedef wmma::fragment<wmma::matrix_b,16,16,8,wmma::precision::tf32,wmma::col_major> FragBc;
typedef wmma::fragment<wmma::accumulator,16,16,8,float> FragC;
typedef wmma::fragment<wmma::matrix_a,16,16,16,__half,wmma::row_major> FragAh;
typedef wmma::fragment<wmma::matrix_b,16,16,16,__half,wmma::row_major> FragBh;
typedef wmma::fragment<wmma::matrix_b,16,16,16,__half,wmma::col_major> FragBhc;
typedef wmma::fragment<wmma::accumulator,16,16,16,float> FragCh;

template<class F> __device__ __forceinline__ void cvt_tf32(F& f){
    #pragma unroll
    for(int i=0;i<f.num_elements;i++) f.x[i]=wmma::__float_to_tf32(f.x[i]);
}

// =======================================================================
// K1: QKV projection (tf32 TC), one launch, z selects Q/K/V; fp16 out.
// =======================================================================
__global__ void __launch_bounds__(256) proj_tc(
    const float* __restrict__ Xq, const float* __restrict__ Xk, const float* __restrict__ Xv,
    const float* __restrict__ Wq, const float* __restrict__ Wk, const float* __restrict__ Wv,
    const float* __restrict__ bq, const float* __restrict__ bk, const float* __restrict__ bv)
{
    __shared__ float sx[128*72];
    int tid=threadIdx.x, w=tid>>5;
    int m0=blockIdx.x*128, o0=blockIdx.y*64;
    int sel=blockIdx.z;
    const float* X   =(sel==0)?Xq:((sel==1)?Xk:Xv);
    const float* W   =(sel==0)?Wq:((sel==1)?Wk:Wv);
    const float* bias=(sel==0)?bq:((sel==1)?bk:bv);
    int wy=w&3, wx=w>>2;
    FragC acc[2][2];
    #pragma unroll
    for(int r=0;r<2;r++)
        #pragma unroll
        for(int c=0;c<2;c++) wmma::fill_fragment(acc[r][c],0.f);

    for(int k0=0;k0<Edim;k0+=8){
        FragA a[2]; FragBc b[2];
        #pragma unroll
        for(int r=0;r<2;r++){
            wmma::load_matrix_sync(a[r], X+(size_t)(m0+wy*32+r*16)*Edim+k0, Edim);
            cvt_tf32(a[r]);
        }
        #pragma unroll
        for(int c=0;c<2;c++){
            wmma::load_matrix_sync(b[c], W+(size_t)(o0+wx*32+c*16)*Edim+k0, Edim);
            cvt_tf32(b[c]);
        }
        #pragma unroll
        for(int r=0;r<2;r++)
            #pragma unroll
            for(int c=0;c<2;c++) wmma::mma_sync(acc[r][c],a[r],b[c],acc[r][c]);
    }
    #pragma unroll
    for(int r=0;r<2;r++)
        #pragma unroll
        for(int c=0;c<2;c++)
            wmma::store_matrix_sync(&sx[(wy*32+r*16)*72+wx*32+c*16],acc[r][c],72,wmma::mem_row_major);
    __syncthreads();

    __half* out=(sel==0)?g_q_h:((sel==1)?g_k_h:g_v_h);
    int r=tid>>1, half=tid&1;
    int m=m0+r, s=m>>3, bb=m&7, h=blockIdx.y;
    size_t base=((size_t)(bb*Hdim+h)*Sdim+s)*Ddim + half*32;
    #pragma unroll
    for(int u=0;u<8;u++){
        int d=half*32+u*4;
        float4 v=*(float4*)&sx[r*72+d];
        v.x+=bias[o0+d]; v.y+=bias[o0+d+1]; v.z+=bias[o0+d+2]; v.w+=bias[o0+d+3];
        __half2 p0=__floats2half2_rn(v.x,v.y), p1=__floats2half2_rn(v.z,v.w);
        uint2 o; o.x=*(unsigned*)&p0; o.y=*(unsigned*)&p1;
        *(uint2*)&out[base+u*4]=o;
    }
}

// =======================================================================
// K2: edge-key bias (fp16 HMMA) -> g_bias_h [j][i][n] fp16
// =======================================================================
__global__ void __launch_bounds__(256) biasgemm_tc(const float* __restrict__ ek)
{
    __shared__ __half s_ekh[64*72];  // [i][d]
    __shared__ __half s_qh[64*72];   // [n][d]
    __shared__ float  s_out[64*68];  // [i][n]
    int tid=threadIdx.x, w=tid>>5;
    int i0=blockIdx.x*64; int j=blockIdx.y;

    const float* ekp = ek + (size_t)j*SD + (size_t)i0*Ddim;  // contiguous 16KB
    for(int idx=tid; idx<1024; idx+=256){
        int r=idx>>4, c=(idx&15)*4;
        float4 v = *(const float4*)&ekp[r*64+c];
        __half2 p0=__floats2half2_rn(v.x,v.y), p1=__floats2half2_rn(v.z,v.w);
        *(__half2*)&s_ekh[r*72+c]   = p0;
        *(__half2*)&s_ekh[r*72+c+2] = p1;
    }
    for(int idx=tid; idx<512; idx+=256){
        int r=idx>>3, c=(idx&7)*8;
        *(uint4*)&s_qh[r*72+c] = *(const uint4*)&g_q_h[(size_t)r*SD+(size_t)j*Ddim+c];
    }
    __syncthreads();

    int wy=w&3, wx=w>>2;  // i strip 16, n half 32
    FragCh acc[2];
    wmma::fill_fragment(acc[0],0.f); wmma::fill_fragment(acc[1],0.f);
    #pragma unroll
    for(int kk=0;kk<4;kk++){
        FragAh a; wmma::load_matrix_sync(a, &s_ekh[(wy*16)*72+kk*16], 72);
        #pragma unroll
        for(int c=0;c<2;c++){
            FragBhc b; wmma::load_matrix_sync(b, &s_qh[(wx*32+c*16)*72+kk*16], 72);
            wmma::mma_sync(acc[c],a,b,acc[c]);
        }
    }
    __syncthreads();
    #pragma unroll
    for(int c=0;c<2;c++)
        wmma::store_matrix_sync(&s_out[(wy*16)*68 + wx*32 + c*16], acc[c], 68, wmma::mem_row_major);
    __syncthreads();

    for(int idx=tid; idx<2048; idx+=256){   // 64 i x 32 half2
        int r=idx>>5, c2=(idx&31)*2;
        __half2 h = __floats2half2_rn(s_out[r*68+c2], s_out[r*68+c2+1]);
        *(__half2*)&g_bias_h[(size_t)j*(Sdim*Ndim)+(size_t)(i0+r)*Ndim + c2] = h;
    }
}

// =======================================================================
// K2b: transpose + mask fold:  g_bias_h[j][i][n] -> g_biasT[n][i][j]
// =======================================================================
__global__ void __launch_bounds__(256) bias_tr(const int* __restrict__ mask)
{
    __shared__ __half t[64][72];   // [j][n]
    int tid=threadIdx.x;
    int i=blockIdx.y, j0=blockIdx.x*64;

    for(int idx=tid; idx<512; idx+=256){
        int r=idx>>3, c=(idx&7)*8;
        *(uint4*)&t[r][c] = *(const uint4*)&g_bias_h[((size_t)(j0+r)*Sdim + i)*Ndim + c];
    }
    __syncthreads();

    int n = tid>>2, jc = tid&3;     // 64 n x 4 chunks of 16 j
    const int* mrow = mask   + ((size_t)n*Sdim + i)*Sdim + j0 + jc*16;
    __half*    dst  = g_biasT + ((size_t)n*Sdim + i)*Sdim + j0 + jc*16;
    const __half hneg = __float2half(-30000.0f);
    #pragma unroll
    for(int u=0;u<2;u++){
        int4 m0 = *(const int4*)&mrow[u*8];
        int4 m1 = *(const int4*)&mrow[u*8+4];
        __half h[8];
        #pragma unroll
        for(int e=0;e<8;e++) h[e] = t[jc*16+u*8+e][n];
        if(m0.x) h[0]=hneg; if(m0.y) h[1]=hneg; if(m0.z) h[2]=hneg; if(m0.w) h[3]=hneg;
        if(m1.x) h[4]=hneg; if(m1.y) h[5]=hneg; if(m1.z) h[6]=hneg; if(m1.w) h[7]=hneg;
        *(uint4*)&dst[u*8] = *(uint4*)h;
    }
}

// =======================================================================
// K3: FUSED score + bias(+mask) + softmax + PV.  (fp16 MMA both GEMMs)
// block = (n, 16 i-rows), 512 threads / 16 warps, 2 blocks/SM.
// smem: s_q 16x72 h | s_l 16x1032 f32 (probs overlaid fp16 in-place) | s_part 4x16x68 f32
// =======================================================================
__global__ void __launch_bounds__(512,2) attn_pv()
{
    extern __shared__ float dsf[];
    __half* s_q  = (__half*)dsf;          // 16 x 72 halfs (2304 B)
    float* s_l   = dsf + 576;             // 16 x 1032 f32
    float* s_part= dsf + 576 + 16*1032;   // 4 x 16 x 68 f32
    int tid=threadIdx.x, w=tid>>5, lane=tid&31;
    int n=blockIdx.x, i0=blockIdx.y*16;

    if(tid<128){
        int r=tid>>3, c=(tid&7)*8;
        *(uint4*)&s_q[r*72+c] = *(const uint4*)&g_q_h[(size_t)n*SD + (size_t)(i0+r)*Ddim + c];
    }
    __syncthreads();

    // ---- phase 1: QK^T (warp w covers j in [w*64, w*64+64)) ----
    {
        FragAh aq[4];
        #pragma unroll
        for(int kk=0;kk<4;kk++) wmma::load_matrix_sync(aq[kk], &s_q[kk*16], 72);
        const __half* kp = g_k_h + (size_t)n*SD + (size_t)(w*64)*Ddim;
        #pragma unroll
        for(int c=0;c<4;c++){
            FragCh acc; wmma::fill_fragment(acc,0.f);
            #pragma unroll
            for(int kk=0;kk<4;kk++){
                FragBhc b; wmma::load_matrix_sync(b, kp + (size_t)(c*16)*Ddim + kk*16, Ddim);
                wmma::mma_sync(acc,aq[kk],b,acc);
            }
            wmma::store_matrix_sync(&s_l[w*64 + c*16], acc, 1032, wmma::mem_row_major);
        }
    }
    __syncthreads();

    // ---- phase 2: softmax on row w; probs -> global fp16 AND fp16 overlay in s_l ----
    {
        int gi = i0 + w;
        const __half* brow = g_biasT  + ((size_t)n*Sdim + gi)*Sdim;
        __half*       prow = g_attn_h + ((size_t)n*Sdim + gi)*Sdim;
        float* lrow = &s_l[w*1032];

        float mx = -1e30f;
        #pragma unroll
        for(int it=0;it<8;it++){
            int jb = it*128 + lane*4;
            float4 l = *(float4*)&lrow[jb];
            uint2 bh = *(const uint2*)&brow[jb];
            const __half2* hp = (const __half2*)&bh;
            float2 b0 = __half22float2(hp[0]);
            float2 b1 = __half22float2(hp[1]);
            l.x=(l.x+b0.x)*0.125f; l.y=(l.y+b0.y)*0.125f;
            l.z=(l.z+b1.x)*0.125f; l.w=(l.w+b1.y)*0.125f;
            mx = fmaxf(mx, fmaxf(fmaxf(l.x,l.y),fmaxf(l.z,l.w)));
            *(float4*)&lrow[jb] = l;
        }
        #pragma unroll
        for(int o=16;o;o>>=1) mx = fmaxf(mx, __shfl_xor_sync(0xffffffffu, mx, o));

        float sm = 0.f;
        #pragma unroll
        for(int it=0;it<8;it++){
            int jb = it*128 + lane*4;
            float4 l = *(float4*)&lrow[jb];
            l.x=__expf(l.x-mx); l.y=__expf(l.y-mx);
            l.z=__expf(l.z-mx); l.w=__expf(l.w-mx);
            sm += (l.x+l.y)+(l.z+l.w);
            *(float4*)&lrow[jb] = l;
        }
        #pragma unroll
        for(int o=16;o;o>>=1) sm += __shfl_xor_sync(0xffffffffu, sm, o);
        float inv = 1.0f/sm;

        __half* hrow = (__half*)lrow;     // fp16 overlay (writes land below reads)
        #pragma unroll
        for(int it=0;it<4;it++){
            int jb = it*256 + lane*8;
            float4 l0 = *(float4*)&lrow[jb];
            float4 l1 = *(float4*)&lrow[jb+4];
            __half2 h0 = __floats2half2_rn(l0.x*inv, l0.y*inv);
            __half2 h1 = __floats2half2_rn(l0.z*inv, l0.w*inv);
            __half2 h2 = __floats2half2_rn(l1.x*inv, l1.y*inv);
            __half2 h3 = __floats2half2_rn(l1.z*inv, l1.w*inv);
            uint4 o4;
            o4.x = *(unsigned*)&h0; o4.y = *(unsigned*)&h1;
            o4.z = *(unsigned*)&h2; o4.w = *(unsigned*)&h3;
            *(uint4*)&prow[jb] = o4;
            *(uint4*)&hrow[jb] = o4;
        }
    }
    __syncthreads();

    // ---- phase 3: PV.  warp (q=w>>2, c=w&3): 16i x 16d over j-quarter q ----
    {
        int q = w>>2, c = w&3;
        const __half* ph = (const __half*)s_l;   // row pitch 2064 halfs
        FragCh acc; wmma::fill_fragment(acc,0.f);
        const __half* vp = g_v_h + (size_t)n*SD + c*16;
        #pragma unroll
        for(int kk=0;kk<16;kk++){
            int jj = q*256 + kk*16;
            FragAh a; wmma::load_matrix_sync(a, ph + jj, 2064);
            FragBh b; wmma::load_matrix_sync(b, vp + (size_t)jj*Ddim, Ddim);
            wmma::mma_sync(acc,a,b,acc);
        }
        wmma::store_matrix_sync(&s_part[q*1088 + c*16], acc, 68, wmma::mem_row_major);
    }
    __syncthreads();

    // ---- phase 4: 4-way reduce, write ctx ----
    if(tid<256){
        int r=tid>>4, db=(tid&15)*4;
        float4 a0=*(float4*)&s_part[0*1088 + r*68 + db];
        float4 a1=*(float4*)&s_part[1*1088 + r*68 + db];
        float4 a2=*(float4*)&s_part[2*1088 + r*68 + db];
        float4 a3=*(float4*)&s_part[3*1088 + r*68 + db];
        float4 o;
        o.x=(a0.x+a1.x)+(a2.x+a3.x);
        o.y=(a0.y+a1.y)+(a2.y+a3.y);
        o.z=(a0.z+a1.z)+(a2.z+a3.z);
        o.w=(a0.w+a1.w)+(a2.w+a3.w);
        *(float4*)&g_ctx[(size_t)(i0+r)*(Bdim*Edim) + n*Ddim + db] = o;
    }
}

// =======================================================================
// K5b: edge-value (fp16 TC).  per i: ctx[i][n*64+d] += p[:,i,:] @ ev[i]
// =======================================================================
__global__ void __launch_bounds__(256) ev_tc(const float* __restrict__ ev)
{
    __shared__ __half ps[64*80];    // [n][j]
    __shared__ __half es[64*80];    // [j][d]
    int tid=threadIdx.x, w=tid>>5;
    int wn=w&3, wd=w>>2;
    int i=blockIdx.x;
    FragCh acc[2];
    #pragma unroll
    for(int c=0;c<2;c++)
        wmma::load_matrix_sync(acc[c],
            &g_ctx[(size_t)i*(Bdim*Edim)+(size_t)(wn*16)*Ddim + wd*32 + c*16],
            Ddim, wmma::mem_row_major);

    for(int j0=0;j0<Sdim;j0+=64){
        for(int idx=tid; idx<512; idx+=256){
            int r=idx>>3, u=(idx&7)*8;
            *(uint4*)&ps[r*80+u] =
                *(const uint4*)&g_attn_h[((size_t)r<<20)+(size_t)i*Sdim + j0 + u];
        }
        for(int idx=tid; idx<1024; idx+=256){
            int r=idx>>4, c=(idx&15)*4;
            float4 v=*(const float4*)&ev[(size_t)i*SD+(size_t)(j0+r)*Ddim+c];
            *(__half2*)&es[r*80+c]   = __floats2half2_rn(v.x,v.y);
            *(__half2*)&es[r*80+c+2] = __floats2half2_rn(v.z,v.w);
        }
        __syncthreads();
        #pragma unroll
        for(int kk=0;kk<4;kk++){
            FragAh a; wmma::load_matrix_sync(a, &ps[(wn*16)*80 + kk*16], 80);
            #pragma unroll
            for(int c=0;c<2;c++){
                FragBh b; wmma::load_matrix_sync(b, &es[(kk*16)*80 + wd*32 + c*16], 80);
                wmma::mma_sync(acc[c],a,b,acc[c]);
            }
        }
        __syncthreads();
    }
    #pragma unroll
    for(int c=0;c<2;c++)
        wmma::store_matrix_sync(&g_ctx[(size_t)i*(Bdim*Edim)+(size_t)(wn*16)*Ddim + wd*32 + c*16],
                                acc[c], Ddim, wmma::mem_row_major);
}

// =======================================================================
// K6: output projection + residual (tf32 TC) -> g_x
// =======================================================================
__global__ void __launch_bounds__(256) outproj_tc(const float* __restrict__ W,
    const float* __restrict__ bias, const float* __restrict__ resid)
{
    __shared__ float sx[128*72];
    int tid=threadIdx.x, w=tid>>5;
    int m0=blockIdx.x*128, o0=blockIdx.y*64;
    int wy=w&3, wx=w>>2;
    FragC acc[2][2];
    #pragma unroll
    for(int r=0;r<2;r++)
        #pragma unroll
        for(int c=0;c<2;c++) wmma::fill_fragment(acc[r][c],0.f);

    for(int k0=0;k0<Edim;k0+=8){
        FragA a[2]; FragBc b[2];
        #pragma unroll
        for(int r=0;r<2;r++){
            wmma::load_matrix_sync(a[r], g_ctx+(size_t)(m0+wy*32+r*16)*Edim+k0, Edim);
            cvt_tf32(a[r]);
        }
        #pragma unroll
        for(int c=0;c<2;c++){
            wmma::load_matrix_sync(b[c], W+(size_t)(o0+wx*32+c*16)*Edim+k0, Edim);
            cvt_tf32(b[c]);
        }
        #pragma unroll
        for(int r=0;r<2;r++)
            #pragma unroll
            for(int c=0;c<2;c++) wmma::mma_sync(acc[r][c],a[r],b[c],acc[r][c]);
    }
    #pragma unroll
    for(int r=0;r<2;r++)
        #pragma unroll
        for(int c=0;c<2;c++)
            wmma::store_matrix_sync(&sx[(wy*32+r*16)*72+wx*32+c*16],acc[r][c],72,wmma::mem_row_major);
    __syncthreads();

    int r=tid>>1, half=tid&1;
    int m=m0+r;
    size_t base=(size_t)m*Edim + o0 + half*32;
    #pragma unroll
    for(int u=0;u<8;u++){
        int d=half*32+u*4;
        float4 v=*(float4*)&sx[r*72+d];
        float4 rs=*(const float4*)&resid[base+u*4];
        v.x+=bias[o0+d]  +rs.x; v.y+=bias[o0+d+1]+rs.y;
        v.z+=bias[o0+d+2]+rs.z; v.w+=bias[o0+d+3]+rs.w;
        *(float4*)&g_x[base+u*4]=v;
    }
}

// =======================================================================
// K7: LayerNorm over last dim (512)
// =======================================================================
__global__ void __launch_bounds__(256) ln_kernel(const float* __restrict__ gamma,
     const float* __restrict__ beta, float* __restrict__ out)
{
    int m = blockIdx.x, tid = threadIdx.x;
    float a = g_x[(size_t)m*Edim + tid];
    float b = g_x[(size_t)m*Edim + 256 + tid];
    __shared__ float s1[256], s2[256];
    s1[tid] = a+b; s2[tid] = a*a + b*b;
    __syncthreads();
    for (int s=128;s>0;s>>=1){
        if(tid<s){ s1[tid]+=s1[tid+s]; s2[tid]+=s2[tid+s]; }
        __syncthreads();
    }
    float mean = s1[0] * (1.0f/512.0f);
    float var  = s2[0] * (1.0f/512.0f) - mean*mean;
    float rstd = rsqrtf(var + 1e-5f);
    out[(size_t)m*Edim + tid]       = gamma[tid]*(a-mean)*rstd + beta[tid];
    out[(size_t)m*Edim + 256 + tid] = gamma[256+tid]*(b-mean)*rstd + beta[256+tid];
}

// =======================================================================
extern "C" void kernel_launch(void* const* d_in, const int* in_sizes, int n_in,
                              void* d_out, int out_size)
{
    const float* query      = (const float*)d_in[0];
    const float* key        = (const float*)d_in[1];
    const float* value      = (const float*)d_in[2];
    const float* edge_key   = (const float*)d_in[3];
    const float* edge_value = (const float*)d_in[4];
    const int*   mask       = (const int*)  d_in[5];
    int base = (n_in == 17) ? 7 : 6;
    const float* Wq = (const float*)d_in[base+0];
    const float* bq = (const float*)d_in[base+1];
    const float* Wk = (const float*)d_in[base+2];
    const float* bk = (const float*)d_in[base+3];
    const float* Wv = (const float*)d_in[base+4];
    const float* bv = (const float*)d_in[base+5];
    const float* Wo = (const float*)d_in[base+6];
    const float* bo = (const float*)d_in[base+7];
    const float* gamma = (const float*)d_in[base+8];
    const float* beta  = (const float*)d_in[base+9];

    // smem: 576 (q) + 16512 (logits) + 4352 (partials) floats = 85760 B
    const int ATTN_SMEM = (576 + 16*1032 + 4*16*68)*4;
    cudaFuncSetAttribute(attn_pv, cudaFuncAttributeMaxDynamicSharedMemorySize, ATTN_SMEM);

    proj_tc<<<dim3(64,8,3),256>>>(query,key,value, Wq,Wk,Wv, bq,bk,bv);
    biasgemm_tc<<<dim3(16,1024),256>>>(edge_key);
    bias_tr<<<dim3(16,1024),256>>>(mask);
    attn_pv<<<dim3(64,64),512,ATTN_SMEM>>>();
    ev_tc<<<1024,256>>>(edge_value);
    outproj_tc<<<dim3(64,8),256>>>(Wo, bo, query);
    ln_kernel<<<dim3(8192),256>>>(gamma, beta, (float*)d_out);
}

// round 13
// speedup vs baseline: 1.0735x; 1.0735x over previous
#include <cuda_runtime.h>
#include <cuda_fp16.h>
#include <mma.h>
#include <math.h>
using namespace nvcuda;

#define Sdim 1024
#define Bdim 8
#define Edim 512
#define Hdim 8
#define Ddim 64
#define Ndim 64   // B*H
#define SD 65536  // Sdim*Ddim

// ---------------- scratch ----------------
__device__ __half g_q_h[(size_t)Ndim*Sdim*Ddim];       // [n][s][d] fp16 8MB
__device__ __half g_k_h[(size_t)Ndim*Sdim*Ddim];
__device__ __half g_v_h[(size_t)Ndim*Sdim*Ddim];
__device__ __half g_bias_h[(size_t)Sdim*Sdim*Ndim];    // [j][i][n] fp16 128MB
__device__ __half g_biasT[(size_t)Ndim*Sdim*Sdim];     // [n][i][j] fp16 (mask folded) 128MB
__device__ __half g_attn_h[(size_t)Ndim*Sdim*Sdim];    // probs fp16 [n][i][j] 128MB
__device__ float  g_ctx[(size_t)Sdim*Bdim*Edim];       // [i][n*64+d]
__device__ float  g_x[(size_t)Sdim*Bdim*Edim];

typedef wmma::fragment<wmma::matrix_a,16,16,8,wmma::precision::tf32,wmma::row_major> FragA;
typedef wmma::fragment<wmma::matrix_b,16,16,8,wmma::precision::tf32,wmma::col_major> FragBc;
typedef wmma::fragment<wmma::accumulator,16,16,8,float> FragC;
typedef wmma::fragment<wmma::matrix_a,16,16,16,__half,wmma::row_major> FragAh;
typedef wmma::fragment<wmma::matrix_b,16,16,16,__half,wmma::row_major> FragBh;
typedef wmma::fragment<wmma::matrix_b,16,16,16,__half,wmma::col_major> FragBhc;
typedef wmma::fragment<wmma::accumulator,16,16,16,float> FragCh;

template<class F> __device__ __forceinline__ void cvt_tf32(F& f){
    #pragma unroll
    for(int i=0;i<f.num_elements;i++) f.x[i]=wmma::__float_to_tf32(f.x[i]);
}

// =======================================================================
// K1: QKV projection (tf32 TC), one launch, z selects Q/K/V; fp16 out.
// =======================================================================
__global__ void __launch_bounds__(256) proj_tc(
    const float* __restrict__ Xq, const float* __restrict__ Xk, const float* __restrict__ Xv,
    const float* __restrict__ Wq, const float* __restrict__ Wk, const float* __restrict__ Wv,
    const float* __restrict__ bq, const float* __restrict__ bk, const float* __restrict__ bv)
{
    __shared__ float sx[128*72];
    int tid=threadIdx.x, w=tid>>5;
    int m0=blockIdx.x*128, o0=blockIdx.y*64;
    int sel=blockIdx.z;
    const float* X   =(sel==0)?Xq:((sel==1)?Xk:Xv);
    const float* W   =(sel==0)?Wq:((sel==1)?Wk:Wv);
    const float* bias=(sel==0)?bq:((sel==1)?bk:bv);
    int wy=w&3, wx=w>>2;
    FragC acc[2][2];
    #pragma unroll
    for(int r=0;r<2;r++)
        #pragma unroll
        for(int c=0;c<2;c++) wmma::fill_fragment(acc[r][c],0.f);

    for(int k0=0;k0<Edim;k0+=8){
        FragA a[2]; FragBc b[2];
        #pragma unroll
        for(int r=0;r<2;r++){
            wmma::load_matrix_sync(a[r], X+(size_t)(m0+wy*32+r*16)*Edim+k0, Edim);
            cvt_tf32(a[r]);
        }
        #pragma unroll
        for(int c=0;c<2;c++){
            wmma::load_matrix_sync(b[c], W+(size_t)(o0+wx*32+c*16)*Edim+k0, Edim);
            cvt_tf32(b[c]);
        }
        #pragma unroll
        for(int r=0;r<2;r++)
            #pragma unroll
            for(int c=0;c<2;c++) wmma::mma_sync(acc[r][c],a[r],b[c],acc[r][c]);
    }
    #pragma unroll
    for(int r=0;r<2;r++)
        #pragma unroll
        for(int c=0;c<2;c++)
            wmma::store_matrix_sync(&sx[(wy*32+r*16)*72+wx*32+c*16],acc[r][c],72,wmma::mem_row_major);
    __syncthreads();

    __half* out=(sel==0)?g_q_h:((sel==1)?g_k_h:g_v_h);
    int r=tid>>1, half=tid&1;
    int m=m0+r, s=m>>3, bb=m&7, h=blockIdx.y;
    size_t base=((size_t)(bb*Hdim+h)*Sdim+s)*Ddim + half*32;
    #pragma unroll
    for(int u=0;u<8;u++){
        int d=half*32+u*4;
        float4 v=*(float4*)&sx[r*72+d];
        v.x+=bias[o0+d]; v.y+=bias[o0+d+1]; v.z+=bias[o0+d+2]; v.w+=bias[o0+d+3];
        __half2 p0=__floats2half2_rn(v.x,v.y), p1=__floats2half2_rn(v.z,v.w);
        uint2 o; o.x=*(unsigned*)&p0; o.y=*(unsigned*)&p1;
        *(uint2*)&out[base+u*4]=o;
    }
}

// =======================================================================
// K2: edge-key bias (fp16 HMMA) -> g_bias_h [j][i][n] fp16
// =======================================================================
__global__ void __launch_bounds__(256) biasgemm_tc(const float* __restrict__ ek)
{
    __shared__ __half s_ekh[64*72];  // [i][d]
    __shared__ __half s_qh[64*72];   // [n][d]
    __shared__ float  s_out[64*68];  // [i][n]
    int tid=threadIdx.x, w=tid>>5;
    int i0=blockIdx.x*64; int j=blockIdx.y;

    const float* ekp = ek + (size_t)j*SD + (size_t)i0*Ddim;  // contiguous 16KB
    for(int idx=tid; idx<1024; idx+=256){
        int r=idx>>4, c=(idx&15)*4;
        float4 v = *(const float4*)&ekp[r*64+c];
        __half2 p0=__floats2half2_rn(v.x,v.y), p1=__floats2half2_rn(v.z,v.w);
        *(__half2*)&s_ekh[r*72+c]   = p0;
        *(__half2*)&s_ekh[r*72+c+2] = p1;
    }
    for(int idx=tid; idx<512; idx+=256){
        int r=idx>>3, c=(idx&7)*8;
        *(uint4*)&s_qh[r*72+c] = *(const uint4*)&g_q_h[(size_t)r*SD+(size_t)j*Ddim+c];
    }
    __syncthreads();

    int wy=w&3, wx=w>>2;  // i strip 16, n half 32
    FragCh acc[2];
    wmma::fill_fragment(acc[0],0.f); wmma::fill_fragment(acc[1],0.f);
    #pragma unroll
    for(int kk=0;kk<4;kk++){
        FragAh a; wmma::load_matrix_sync(a, &s_ekh[(wy*16)*72+kk*16], 72);
        #pragma unroll
        for(int c=0;c<2;c++){
            FragBhc b; wmma::load_matrix_sync(b, &s_qh[(wx*32+c*16)*72+kk*16], 72);
            wmma::mma_sync(acc[c],a,b,acc[c]);
        }
    }
    __syncthreads();
    #pragma unroll
    for(int c=0;c<2;c++)
        wmma::store_matrix_sync(&s_out[(wy*16)*68 + wx*32 + c*16], acc[c], 68, wmma::mem_row_major);
    __syncthreads();

    for(int idx=tid; idx<2048; idx+=256){   // 64 i x 32 half2
        int r=idx>>5, c2=(idx&31)*2;
        __half2 h = __floats2half2_rn(s_out[r*68+c2], s_out[r*68+c2+1]);
        *(__half2*)&g_bias_h[(size_t)j*(Sdim*Ndim)+(size_t)(i0+r)*Ndim + c2] = h;
    }
}

// =======================================================================
// K2b: transpose + mask fold:  g_bias_h[j][i][n] -> g_biasT[n][i][j]
// =======================================================================
__global__ void __launch_bounds__(256) bias_tr(const int* __restrict__ mask)
{
    __shared__ __half t[64][72];   // [j][n]
    int tid=threadIdx.x;
    int i=blockIdx.y, j0=blockIdx.x*64;

    for(int idx=tid; idx<512; idx+=256){
        int r=idx>>3, c=(idx&7)*8;
        *(uint4*)&t[r][c] = *(const uint4*)&g_bias_h[((size_t)(j0+r)*Sdim + i)*Ndim + c];
    }
    __syncthreads();

    int n = tid>>2, jc = tid&3;     // 64 n x 4 chunks of 16 j
    const int* mrow = mask   + ((size_t)n*Sdim + i)*Sdim + j0 + jc*16;
    __half*    dst  = g_biasT + ((size_t)n*Sdim + i)*Sdim + j0 + jc*16;
    const __half hneg = __float2half(-30000.0f);
    #pragma unroll
    for(int u=0;u<2;u++){
        int4 m0 = *(const int4*)&mrow[u*8];
        int4 m1 = *(const int4*)&mrow[u*8+4];
        __half h[8];
        #pragma unroll
        for(int e=0;e<8;e++) h[e] = t[jc*16+u*8+e][n];
        if(m0.x) h[0]=hneg; if(m0.y) h[1]=hneg; if(m0.z) h[2]=hneg; if(m0.w) h[3]=hneg;
        if(m1.x) h[4]=hneg; if(m1.y) h[5]=hneg; if(m1.z) h[6]=hneg; if(m1.w) h[7]=hneg;
        *(uint4*)&dst[u*8] = *(uint4*)h;
    }
}

// =======================================================================
// K3: FUSED score + bias(+mask) + softmax -> fp16 probs.  (fp16 QK MMA)
// block = (n, 16 i-rows), 512 threads / 16 warps, 2 blocks/SM.
// =======================================================================
__global__ void __launch_bounds__(512,2) attn_sm()
{
    extern __shared__ float dsf[];
    __half* s_q  = (__half*)dsf;          // 16 x 72 halfs (2304 B)
    float* s_logit = dsf + 576;           // 16 x 1032 f32
    int tid=threadIdx.x, w=tid>>5, lane=tid&31;
    int n=blockIdx.x, i0=blockIdx.y*16;

    if(tid<128){
        int r=tid>>3, c=(tid&7)*8;
        *(uint4*)&s_q[r*72+c] = *(const uint4*)&g_q_h[(size_t)n*SD + (size_t)(i0+r)*Ddim + c];
    }
    __syncthreads();

    // ---- phase 1: QK^T (warp w covers j in [w*64, w*64+64)) ----
    {
        FragAh aq[4];
        #pragma unroll
        for(int kk=0;kk<4;kk++) wmma::load_matrix_sync(aq[kk], &s_q[kk*16], 72);
        const __half* kp = g_k_h + (size_t)n*SD + (size_t)(w*64)*Ddim;
        #pragma unroll
        for(int c=0;c<4;c++){
            FragCh acc; wmma::fill_fragment(acc,0.f);
            #pragma unroll
            for(int kk=0;kk<4;kk++){
                FragBhc b; wmma::load_matrix_sync(b, kp + (size_t)(c*16)*Ddim + kk*16, Ddim);
                wmma::mma_sync(acc,aq[kk],b,acc);
            }
            wmma::store_matrix_sync(&s_logit[w*64 + c*16], acc, 1032, wmma::mem_row_major);
        }
    }
    __syncthreads();

    // ---- phase 2: softmax on row w (smem sweeps) ----
    int gi = i0 + w;
    const __half* brow = g_biasT  + ((size_t)n*Sdim + gi)*Sdim;
    __half*       prow = g_attn_h + ((size_t)n*Sdim + gi)*Sdim;
    float* lrow = &s_logit[w*1032];

    float mx = -1e30f;
    #pragma unroll
    for(int it=0;it<8;it++){
        int jb = it*128 + lane*4;
        float4 l = *(float4*)&lrow[jb];
        uint2 bh = *(const uint2*)&brow[jb];
        const __half2* hp = (const __half2*)&bh;
        float2 b0 = __half22float2(hp[0]);
        float2 b1 = __half22float2(hp[1]);
        l.x=(l.x+b0.x)*0.125f; l.y=(l.y+b0.y)*0.125f;
        l.z=(l.z+b1.x)*0.125f; l.w=(l.w+b1.y)*0.125f;
        mx = fmaxf(mx, fmaxf(fmaxf(l.x,l.y),fmaxf(l.z,l.w)));
        *(float4*)&lrow[jb] = l;
    }
    #pragma unroll
    for(int o=16;o;o>>=1) mx = fmaxf(mx, __shfl_xor_sync(0xffffffffu, mx, o));

    float sm = 0.f;
    #pragma unroll
    for(int it=0;it<8;it++){
        int jb = it*128 + lane*4;
        float4 l = *(float4*)&lrow[jb];
        l.x=__expf(l.x-mx); l.y=__expf(l.y-mx);
        l.z=__expf(l.z-mx); l.w=__expf(l.w-mx);
        sm += (l.x+l.y)+(l.z+l.w);
        *(float4*)&lrow[jb] = l;
    }
    #pragma unroll
    for(int o=16;o;o>>=1) sm += __shfl_xor_sync(0xffffffffu, sm, o);
    float inv = 1.0f/sm;

    #pragma unroll
    for(int it=0;it<4;it++){
        int jb = it*256 + lane*8;
        float4 l0 = *(float4*)&lrow[jb];
        float4 l1 = *(float4*)&lrow[jb+4];
        __half2 h0 = __floats2half2_rn(l0.x*inv, l0.y*inv);
        __half2 h1 = __floats2half2_rn(l0.z*inv, l0.w*inv);
        __half2 h2 = __floats2half2_rn(l1.x*inv, l1.y*inv);
        __half2 h3 = __floats2half2_rn(l1.z*inv, l1.w*inv);
        uint4 o4;
        o4.x = *(unsigned*)&h0; o4.y = *(unsigned*)&h1;
        o4.z = *(unsigned*)&h2; o4.w = *(unsigned*)&h3;
        *(uint4*)&prow[jb] = o4;
    }
}

// =======================================================================
// K5a: PV (fp16 TC).  ctx[i][n*64+d] = sum_j p[n,i,j]*v[n,j,d]
// =======================================================================
__global__ void __launch_bounds__(256) pv_tc()
{
    __shared__ __half ps[128*80];   // [i][j]
    __shared__ __half vs[64*80];    // [j][d]
    int tid=threadIdx.x, w=tid>>5;
    int i0=blockIdx.x*128, n=blockIdx.y;
    FragCh acc[4];
    #pragma unroll
    for(int c=0;c<4;c++) wmma::fill_fragment(acc[c],0.f);

    for(int j0=0;j0<Sdim;j0+=64){
        for(int idx=tid; idx<1024; idx+=256){
            int r=idx>>3, u=(idx&7)*8;
            *(uint4*)&ps[r*80+u] =
                *(const uint4*)&g_attn_h[((size_t)n<<20)+(size_t)(i0+r)*Sdim + j0 + u];
        }
        for(int idx=tid; idx<512; idx+=256){
            int r=idx>>3, u=(idx&7)*8;
            *(uint4*)&vs[r*80+u] =
                *(const uint4*)&g_v_h[(size_t)n*SD+(size_t)(j0+r)*Ddim + u];
        }
        __syncthreads();
        #pragma unroll
        for(int kk=0;kk<4;kk++){
            FragAh a; wmma::load_matrix_sync(a, &ps[(w*16)*80 + kk*16], 80);
            #pragma unroll
            for(int c=0;c<4;c++){
                FragBh b; wmma::load_matrix_sync(b, &vs[(kk*16)*80 + c*16], 80);
                wmma::mma_sync(acc[c],a,b,acc[c]);
            }
        }
        __syncthreads();
    }
    #pragma unroll
    for(int c=0;c<4;c++)
        wmma::store_matrix_sync(&g_ctx[(size_t)(i0+w*16)*(Bdim*Edim)+(size_t)n*Ddim+c*16],
                                acc[c], Bdim*Edim, wmma::mem_row_major);
}

// =======================================================================
// K5b: edge-value (fp16 TC).  per i: ctx[i][n*64+d] += p[:,i,:] @ ev[i]
// =======================================================================
__global__ void __launch_bounds__(256) ev_tc(const float* __restrict__ ev)
{
    __shared__ __half ps[64*80];    // [n][j]
    __shared__ __half es[64*80];    // [j][d]
    int tid=threadIdx.x, w=tid>>5;
    int wn=w&3, wd=w>>2;
    int i=blockIdx.x;
    FragCh acc[2];
    #pragma unroll
    for(int c=0;c<2;c++)
        wmma::load_matrix_sync(acc[c],
            &g_ctx[(size_t)i*(Bdim*Edim)+(size_t)(wn*16)*Ddim + wd*32 + c*16],
            Ddim, wmma::mem_row_major);

    for(int j0=0;j0<Sdim;j0+=64){
        for(int idx=tid; idx<512; idx+=256){
            int r=idx>>3, u=(idx&7)*8;
            *(uint4*)&ps[r*80+u] =
                *(const uint4*)&g_attn_h[((size_t)r<<20)+(size_t)i*Sdim + j0 + u];
        }
        for(int idx=tid; idx<1024; idx+=256){
            int r=idx>>4, c=(idx&15)*4;
            float4 v=*(const float4*)&ev[(size_t)i*SD+(size_t)(j0+r)*Ddim+c];
            *(__half2*)&es[r*80+c]   = __floats2half2_rn(v.x,v.y);
            *(__half2*)&es[r*80+c+2] = __floats2half2_rn(v.z,v.w);
        }
        __syncthreads();
        #pragma unroll
        for(int kk=0;kk<4;kk++){
            FragAh a; wmma::load_matrix_sync(a, &ps[(wn*16)*80 + kk*16], 80);
            #pragma unroll
            for(int c=0;c<2;c++){
                FragBh b; wmma::load_matrix_sync(b, &es[(kk*16)*80 + wd*32 + c*16], 80);
                wmma::mma_sync(acc[c],a,b,acc[c]);
            }
        }
        __syncthreads();
    }
    #pragma unroll
    for(int c=0;c<2;c++)
        wmma::store_matrix_sync(&g_ctx[(size_t)i*(Bdim*Edim)+(size_t)(wn*16)*Ddim + wd*32 + c*16],
                                acc[c], Ddim, wmma::mem_row_major);
}

// =======================================================================
// K6: output projection + residual (tf32 TC) -> g_x
// =======================================================================
__global__ void __launch_bounds__(256) outproj_tc(const float* __restrict__ W,
    const float* __restrict__ bias, const float* __restrict__ resid)
{
    __shared__ float sx[128*72];
    int tid=threadIdx.x, w=tid>>5;
    int m0=blockIdx.x*128, o0=blockIdx.y*64;
    int wy=w&3, wx=w>>2;
    FragC acc[2][2];
    #pragma unroll
    for(int r=0;r<2;r++)
        #pragma unroll
        for(int c=0;c<2;c++) wmma::fill_fragment(acc[r][c],0.f);

    for(int k0=0;k0<Edim;k0+=8){
        FragA a[2]; FragBc b[2];
        #pragma unroll
        for(int r=0;r<2;r++){
            wmma::load_matrix_sync(a[r], g_ctx+(size_t)(m0+wy*32+r*16)*Edim+k0, Edim);
            cvt_tf32(a[r]);
        }
        #pragma unroll
        for(int c=0;c<2;c++){
            wmma::load_matrix_sync(b[c], W+(size_t)(o0+wx*32+c*16)*Edim+k0, Edim);
            cvt_tf32(b[c]);
        }
        #pragma unroll
        for(int r=0;r<2;r++)
            #pragma unroll
            for(int c=0;c<2;c++) wmma::mma_sync(acc[r][c],a[r],b[c],acc[r][c]);
    }
    #pragma unroll
    for(int r=0;r<2;r++)
        #pragma unroll
        for(int c=0;c<2;c++)
            wmma::store_matrix_sync(&sx[(wy*32+r*16)*72+wx*32+c*16],acc[r][c],72,wmma::mem_row_major);
    __syncthreads();

    int r=tid>>1, half=tid&1;
    int m=m0+r;
    size_t base=(size_t)m*Edim + o0 + half*32;
    #pragma unroll
    for(int u=0;u<8;u++){
        int d=half*32+u*4;
        float4 v=*(float4*)&sx[r*72+d];
        float4 rs=*(const float4*)&resid[base+u*4];
        v.x+=bias[o0+d]  +rs.x; v.y+=bias[o0+d+1]+rs.y;
        v.z+=bias[o0+d+2]+rs.z; v.w+=bias[o0+d+3]+rs.w;
        *(float4*)&g_x[base+u*4]=v;
    }
}

// =======================================================================
// K7: LayerNorm over last dim (512)
// =======================================================================
__global__ void __launch_bounds__(256) ln_kernel(const float* __restrict__ gamma,
     const float* __restrict__ beta, float* __restrict__ out)
{
    int m = blockIdx.x, tid = threadIdx.x;
    float a = g_x[(size_t)m*Edim + tid];
    float b = g_x[(size_t)m*Edim + 256 + tid];
    __shared__ float s1[256], s2[256];
    s1[tid] = a+b; s2[tid] = a*a + b*b;
    __syncthreads();
    for (int s=128;s>0;s>>=1){
        if(tid<s){ s1[tid]+=s1[tid+s]; s2[tid]+=s2[tid+s]; }
        __syncthreads();
    }
    float mean = s1[0] * (1.0f/512.0f);
    float var  = s2[0] * (1.0f/512.0f) - mean*mean;
    float rstd = rsqrtf(var + 1e-5f);
    out[(size_t)m*Edim + tid]       = gamma[tid]*(a-mean)*rstd + beta[tid];
    out[(size_t)m*Edim + 256 + tid] = gamma[256+tid]*(b-mean)*rstd + beta[256+tid];
}

// =======================================================================
extern "C" void kernel_launch(void* const* d_in, const int* in_sizes, int n_in,
                              void* d_out, int out_size)
{
    const float* query      = (const float*)d_in[0];
    const float* key        = (const float*)d_in[1];
    const float* value      = (const float*)d_in[2];
    const float* edge_key   = (const float*)d_in[3];
    const float* edge_value = (const float*)d_in[4];
    const int*   mask       = (const int*)  d_in[5];
    int base = (n_in == 17) ? 7 : 6;
    const float* Wq = (const float*)d_in[base+0];
    const float* bq = (const float*)d_in[base+1];
    const float* Wk = (const float*)d_in[base+2];
    const float* bk = (const float*)d_in[base+3];
    const float* Wv = (const float*)d_in[base+4];
    const float* bv = (const float*)d_in[base+5];
    const float* Wo = (const float*)d_in[base+6];
    const float* bo = (const float*)d_in[base+7];
    const float* gamma = (const float*)d_in[base+8];
    const float* beta  = (const float*)d_in[base+9];

    // smem: 576 f32 (q halfs) + 16*1032 f32 logits = 68352 B
    const int ATTN_SMEM = (576 + 16*1032)*4;
    cudaFuncSetAttribute(attn_sm, cudaFuncAttributeMaxDynamicSharedMemorySize, ATTN_SMEM);

    proj_tc<<<dim3(64,8,3),256>>>(query,key,value, Wq,Wk,Wv, bq,bk,bv);
    biasgemm_tc<<<dim3(16,1024),256>>>(edge_key);
    bias_tr<<<dim3(16,1024),256>>>(mask);
    attn_sm<<<dim3(64,64),512,ATTN_SMEM>>>();
    pv_tc<<<dim3(8,64),256>>>();
    ev_tc<<<1024,256>>>(edge_value);
    outproj_tc<<<dim3(64,8),256>>>(Wo, bo, query);
    ln_kernel<<<dim3(8192),256>>>(gamma, beta, (float*)d_out);
}

// round 14
// speedup vs baseline: 1.1155x; 1.0391x over previous
#include <cuda_runtime.h>
#include <cuda_fp16.h>
#include <mma.h>
#include <math.h>
using namespace nvcuda;

#define Sdim 1024
#define Bdim 8
#define Edim 512
#define Hdim 8
#define Ddim 64
#define Ndim 64   // B*H
#define SD 65536  // Sdim*Ddim

// ---------------- scratch ----------------
__device__ __half g_q_h[(size_t)Ndim*Sdim*Ddim];       // [n][s][d] fp16 8MB
__device__ __half g_k_h[(size_t)Ndim*Sdim*Ddim];
__device__ __half g_v_h[(size_t)Ndim*Sdim*Ddim];
__device__ __half g_bias_h[(size_t)Sdim*Sdim*Ndim];    // [j][i][n] fp16 128MB
__device__ __half g_biasT[(size_t)Ndim*Sdim*Sdim];     // [n][i][j] fp16 (mask folded) 128MB
__device__ __half g_attn_h[(size_t)Ndim*Sdim*Sdim];    // probs fp16 [n][i][j] 128MB
__device__ float  g_ctx[(size_t)Sdim*Bdim*Edim];       // [i][n*64+d]
__device__ float  g_x[(size_t)Sdim*Bdim*Edim];

typedef wmma::fragment<wmma::matrix_a,16,16,8,wmma::precision::tf32,wmma::row_major> FragA;
typedef wmma::fragment<wmma::matrix_b,16,16,8,wmma::precision::tf32,wmma::col_major> FragBc;
typedef wmma::fragment<wmma::accumulator,16,16,8,float> FragC;
typedef wmma::fragment<wmma::matrix_a,16,16,16,__half,wmma::row_major> FragAh;
typedef wmma::fragment<wmma::matrix_b,16,16,16,__half,wmma::row_major> FragBh;
typedef wmma::fragment<wmma::matrix_b,16,16,16,__half,wmma::col_major> FragBhc;
typedef wmma::fragment<wmma::accumulator,16,16,16,float> FragCh;

template<class F> __device__ __forceinline__ void cvt_tf32(F& f){
    #pragma unroll
    for(int i=0;i<f.num_elements;i++) f.x[i]=wmma::__float_to_tf32(f.x[i]);
}

// =======================================================================
// K1: QKV projection (tf32 TC), one launch, z selects Q/K/V; fp16 out.
// =======================================================================
__global__ void __launch_bounds__(256) proj_tc(
    const float* __restrict__ Xq, const float* __restrict__ Xk, const float* __restrict__ Xv,
    const float* __restrict__ Wq, const float* __restrict__ Wk, const float* __restrict__ Wv,
    const float* __restrict__ bq, const float* __restrict__ bk, const float* __restrict__ bv)
{
    __shared__ float sx[128*72];
    int tid=threadIdx.x, w=tid>>5;
    int m0=blockIdx.x*128, o0=blockIdx.y*64;
    int sel=blockIdx.z;
    const float* X   =(sel==0)?Xq:((sel==1)?Xk:Xv);
    const float* W   =(sel==0)?Wq:((sel==1)?Wk:Wv);
    const float* bias=(sel==0)?bq:((sel==1)?bk:bv);
    int wy=w&3, wx=w>>2;
    FragC acc[2][2];
    #pragma unroll
    for(int r=0;r<2;r++)
        #pragma unroll
        for(int c=0;c<2;c++) wmma::fill_fragment(acc[r][c],0.f);

    for(int k0=0;k0<Edim;k0+=8){
        FragA a[2]; FragBc b[2];
        #pragma unroll
        for(int r=0;r<2;r++){
            wmma::load_matrix_sync(a[r], X+(size_t)(m0+wy*32+r*16)*Edim+k0, Edim);
            cvt_tf32(a[r]);
        }
        #pragma unroll
        for(int c=0;c<2;c++){
            wmma::load_matrix_sync(b[c], W+(size_t)(o0+wx*32+c*16)*Edim+k0, Edim);
            cvt_tf32(b[c]);
        }
        #pragma unroll
        for(int r=0;r<2;r++)
            #pragma unroll
            for(int c=0;c<2;c++) wmma::mma_sync(acc[r][c],a[r],b[c],acc[r][c]);
    }
    #pragma unroll
    for(int r=0;r<2;r++)
        #pragma unroll
        for(int c=0;c<2;c++)
            wmma::store_matrix_sync(&sx[(wy*32+r*16)*72+wx*32+c*16],acc[r][c],72,wmma::mem_row_major);
    __syncthreads();

    __half* out=(sel==0)?g_q_h:((sel==1)?g_k_h:g_v_h);
    int r=tid>>1, half=tid&1;
    int m=m0+r, s=m>>3, bb=m&7, h=blockIdx.y;
    size_t base=((size_t)(bb*Hdim+h)*Sdim+s)*Ddim + half*32;
    #pragma unroll
    for(int u=0;u<8;u++){
        int d=half*32+u*4;
        float4 v=*(float4*)&sx[r*72+d];
        v.x+=bias[o0+d]; v.y+=bias[o0+d+1]; v.z+=bias[o0+d+2]; v.w+=bias[o0+d+3];
        __half2 p0=__floats2half2_rn(v.x,v.y), p1=__floats2half2_rn(v.z,v.w);
        uint2 o; o.x=*(unsigned*)&p0; o.y=*(unsigned*)&p1;
        *(uint2*)&out[base+u*4]=o;
    }
}

// =======================================================================
// K2: edge-key bias (fp16 HMMA) -> g_bias_h [j][i][n] fp16
// =======================================================================
__global__ void __launch_bounds__(256) biasgemm_tc(const float* __restrict__ ek)
{
    __shared__ __half s_ekh[64*72];  // [i][d]
    __shared__ __half s_qh[64*72];   // [n][d]
    __shared__ float  s_out[64*68];  // [i][n]
    int tid=threadIdx.x, w=tid>>5;
    int i0=blockIdx.x*64; int j=blockIdx.y;

    const float* ekp = ek + (size_t)j*SD + (size_t)i0*Ddim;  // contiguous 16KB
    for(int idx=tid; idx<1024; idx+=256){
        int r=idx>>4, c=(idx&15)*4;
        float4 v = *(const float4*)&ekp[r*64+c];
        __half2 p0=__floats2half2_rn(v.x,v.y), p1=__floats2half2_rn(v.z,v.w);
        *(__half2*)&s_ekh[r*72+c]   = p0;
        *(__half2*)&s_ekh[r*72+c+2] = p1;
    }
    for(int idx=tid; idx<512; idx+=256){
        int r=idx>>3, c=(idx&7)*8;
        *(uint4*)&s_qh[r*72+c] = *(const uint4*)&g_q_h[(size_t)r*SD+(size_t)j*Ddim+c];
    }
    __syncthreads();

    int wy=w&3, wx=w>>2;  // i strip 16, n half 32
    FragCh acc[2];
    wmma::fill_fragment(acc[0],0.f); wmma::fill_fragment(acc[1],0.f);
    #pragma unroll
    for(int kk=0;kk<4;kk++){
        FragAh a; wmma::load_matrix_sync(a, &s_ekh[(wy*16)*72+kk*16], 72);
        #pragma unroll
        for(int c=0;c<2;c++){
            FragBhc b; wmma::load_matrix_sync(b, &s_qh[(wx*32+c*16)*72+kk*16], 72);
            wmma::mma_sync(acc[c],a,b,acc[c]);
        }
    }
    __syncthreads();
    #pragma unroll
    for(int c=0;c<2;c++)
        wmma::store_matrix_sync(&s_out[(wy*16)*68 + wx*32 + c*16], acc[c], 68, wmma::mem_row_major);
    __syncthreads();

    for(int idx=tid; idx<2048; idx+=256){   // 64 i x 32 half2
        int r=idx>>5, c2=(idx&31)*2;
        __half2 h = __floats2half2_rn(s_out[r*68+c2], s_out[r*68+c2+1]);
        *(__half2*)&g_bias_h[(size_t)j*(Sdim*Ndim)+(size_t)(i0+r)*Ndim + c2] = h;
    }
}

// =======================================================================
// K2b: transpose + mask fold:  g_bias_h[j][i][n] -> g_biasT[n][i][j]
// =======================================================================
__global__ void __launch_bounds__(256) bias_tr(const int* __restrict__ mask)
{
    __shared__ __half t[64][72];   // [j][n]
    int tid=threadIdx.x;
    int i=blockIdx.y, j0=blockIdx.x*64;

    for(int idx=tid; idx<512; idx+=256){
        int r=idx>>3, c=(idx&7)*8;
        *(uint4*)&t[r][c] = *(const uint4*)&g_bias_h[((size_t)(j0+r)*Sdim + i)*Ndim + c];
    }
    __syncthreads();

    int n = tid>>2, jc = tid&3;     // 64 n x 4 chunks of 16 j
    const int* mrow = mask   + ((size_t)n*Sdim + i)*Sdim + j0 + jc*16;
    __half*    dst  = g_biasT + ((size_t)n*Sdim + i)*Sdim + j0 + jc*16;
    const __half hneg = __float2half(-30000.0f);
    #pragma unroll
    for(int u=0;u<2;u++){
        int4 m0 = *(const int4*)&mrow[u*8];
        int4 m1 = *(const int4*)&mrow[u*8+4];
        __half h[8];
        #pragma unroll
        for(int e=0;e<8;e++) h[e] = t[jc*16+u*8+e][n];
        if(m0.x) h[0]=hneg; if(m0.y) h[1]=hneg; if(m0.z) h[2]=hneg; if(m0.w) h[3]=hneg;
        if(m1.x) h[4]=hneg; if(m1.y) h[5]=hneg; if(m1.z) h[6]=hneg; if(m1.w) h[7]=hneg;
        *(uint4*)&dst[u*8] = *(uint4*)h;
    }
}

// =======================================================================
// K3: FUSED score + bias(+mask) + softmax -> fp16 probs.  (fp16 QK MMA)
// block = (n, 16 i-rows), 512 threads / 16 warps, 2 blocks/SM.
// K staged through smem in 256-row chunks (coalesced uint4).
// smem: s_q 16x72 h | s_logit 16x1032 f32 | s_k 256x72 h  = 105216 B
// =======================================================================
__global__ void __launch_bounds__(512,2) attn_sm()
{
    extern __shared__ float dsf[];
    __half* s_q    = (__half*)dsf;                    // 16 x 72 halfs
    float*  s_logit= dsf + 576;                       // 16 x 1032 f32
    __half* s_k    = (__half*)(dsf + 576 + 16*1032);  // 256 x 72 halfs
    int tid=threadIdx.x, w=tid>>5, lane=tid&31;
    int n=blockIdx.x, i0=blockIdx.y*16;

    if(tid<128){
        int r=tid>>3, c=(tid&7)*8;
        *(uint4*)&s_q[r*72+c] = *(const uint4*)&g_q_h[(size_t)n*SD + (size_t)(i0+r)*Ddim + c];
    }
    __syncthreads();

    // ---- phase 1: QK^T, K staged via smem ----
    {
        FragAh aq[4];
        #pragma unroll
        for(int kk=0;kk<4;kk++) wmma::load_matrix_sync(aq[kk], &s_q[kk*16], 72);

        for(int j0=0;j0<Sdim;j0+=256){
            // cooperative K chunk load: 256 rows x 64 halfs = 2048 uint4
            const __half* kp = g_k_h + (size_t)n*SD + (size_t)j0*Ddim;
            #pragma unroll
            for(int it=0;it<4;it++){
                int idx = tid + it*512;
                int r=idx>>3, u=(idx&7)*8;
                *(uint4*)&s_k[r*72+u] = *(const uint4*)&kp[(size_t)r*Ddim + u];
            }
            __syncthreads();
            // warp w: j-subtile [j0 + w*16, +16)
            FragCh acc; wmma::fill_fragment(acc,0.f);
            #pragma unroll
            for(int kk=0;kk<4;kk++){
                FragBhc b; wmma::load_matrix_sync(b, &s_k[(w*16)*72 + kk*16], 72);
                wmma::mma_sync(acc,aq[kk],b,acc);
            }
            wmma::store_matrix_sync(&s_logit[j0 + w*16], acc, 1032, wmma::mem_row_major);
            __syncthreads();
        }
    }

    // ---- phase 2: softmax on row w (smem sweeps) ----
    int gi = i0 + w;
    const __half* brow = g_biasT  + ((size_t)n*Sdim + gi)*Sdim;
    __half*       prow = g_attn_h + ((size_t)n*Sdim + gi)*Sdim;
    float* lrow = &s_logit[w*1032];

    float mx = -1e30f;
    #pragma unroll
    for(int it=0;it<8;it++){
        int jb = it*128 + lane*4;
        float4 l = *(float4*)&lrow[jb];
        uint2 bh = *(const uint2*)&brow[jb];
        const __half2* hp = (const __half2*)&bh;
        float2 b0 = __half22float2(hp[0]);
        float2 b1 = __half22float2(hp[1]);
        l.x=(l.x+b0.x)*0.125f; l.y=(l.y+b0.y)*0.125f;
        l.z=(l.z+b1.x)*0.125f; l.w=(l.w+b1.y)*0.125f;
        mx = fmaxf(mx, fmaxf(fmaxf(l.x,l.y),fmaxf(l.z,l.w)));
        *(float4*)&lrow[jb] = l;
    }
    #pragma unroll
    for(int o=16;o;o>>=1) mx = fmaxf(mx, __shfl_xor_sync(0xffffffffu, mx, o));

    float sm = 0.f;
    #pragma unroll
    for(int it=0;it<8;it++){
        int jb = it*128 + lane*4;
        float4 l = *(float4*)&lrow[jb];
        l.x=__expf(l.x-mx); l.y=__expf(l.y-mx);
        l.z=__expf(l.z-mx); l.w=__expf(l.w-mx);
        sm += (l.x+l.y)+(l.z+l.w);
        *(float4*)&lrow[jb] = l;
    }
    #pragma unroll
    for(int o=16;o;o>>=1) sm += __shfl_xor_sync(0xffffffffu, sm, o);
    float inv = 1.0f/sm;

    #pragma unroll
    for(int it=0;it<4;it++){
        int jb = it*256 + lane*8;
        float4 l0 = *(float4*)&lrow[jb];
        float4 l1 = *(float4*)&lrow[jb+4];
        __half2 h0 = __floats2half2_rn(l0.x*inv, l0.y*inv);
        __half2 h1 = __floats2half2_rn(l0.z*inv, l0.w*inv);
        __half2 h2 = __floats2half2_rn(l1.x*inv, l1.y*inv);
        __half2 h3 = __floats2half2_rn(l1.z*inv, l1.w*inv);
        uint4 o4;
        o4.x = *(unsigned*)&h0; o4.y = *(unsigned*)&h1;
        o4.z = *(unsigned*)&h2; o4.w = *(unsigned*)&h3;
        *(uint4*)&prow[jb] = o4;
    }
}

// =======================================================================
// K5a: PV (fp16 TC).  ctx[i][n*64+d] = sum_j p[n,i,j]*v[n,j,d]
// =======================================================================
__global__ void __launch_bounds__(256) pv_tc()
{
    __shared__ __half ps[128*80];   // [i][j]
    __shared__ __half vs[64*80];    // [j][d]
    int tid=threadIdx.x, w=tid>>5;
    int i0=blockIdx.x*128, n=blockIdx.y;
    FragCh acc[4];
    #pragma unroll
    for(int c=0;c<4;c++) wmma::fill_fragment(acc[c],0.f);

    for(int j0=0;j0<Sdim;j0+=64){
        for(int idx=tid; idx<1024; idx+=256){
            int r=idx>>3, u=(idx&7)*8;
            *(uint4*)&ps[r*80+u] =
                *(const uint4*)&g_attn_h[((size_t)n<<20)+(size_t)(i0+r)*Sdim + j0 + u];
        }
        for(int idx=tid; idx<512; idx+=256){
            int r=idx>>3, u=(idx&7)*8;
            *(uint4*)&vs[r*80+u] =
                *(const uint4*)&g_v_h[(size_t)n*SD+(size_t)(j0+r)*Ddim + u];
        }
        __syncthreads();
        #pragma unroll
        for(int kk=0;kk<4;kk++){
            FragAh a; wmma::load_matrix_sync(a, &ps[(w*16)*80 + kk*16], 80);
            #pragma unroll
            for(int c=0;c<4;c++){
                FragBh b; wmma::load_matrix_sync(b, &vs[(kk*16)*80 + c*16], 80);
                wmma::mma_sync(acc[c],a,b,acc[c]);
            }
        }
        __syncthreads();
    }
    #pragma unroll
    for(int c=0;c<4;c++)
        wmma::store_matrix_sync(&g_ctx[(size_t)(i0+w*16)*(Bdim*Edim)+(size_t)n*Ddim+c*16],
                                acc[c], Bdim*Edim, wmma::mem_row_major);
}

// =======================================================================
// K5b: edge-value (fp16 TC).  per i: ctx[i][n*64+d] += p[:,i,:] @ ev[i]
// =======================================================================
__global__ void __launch_bounds__(256) ev_tc(const float* __restrict__ ev)
{
    __shared__ __half ps[64*80];    // [n][j]
    __shared__ __half es[64*80];    // [j][d]
    int tid=threadIdx.x, w=tid>>5;
    int wn=w&3, wd=w>>2;
    int i=blockIdx.x;
    FragCh acc[2];
    #pragma unroll
    for(int c=0;c<2;c++)
        wmma::load_matrix_sync(acc[c],
            &g_ctx[(size_t)i*(Bdim*Edim)+(size_t)(wn*16)*Ddim + wd*32 + c*16],
            Ddim, wmma::mem_row_major);

    for(int j0=0;j0<Sdim;j0+=64){
        for(int idx=tid; idx<512; idx+=256){
            int r=idx>>3, u=(idx&7)*8;
            *(uint4*)&ps[r*80+u] =
                *(const uint4*)&g_attn_h[((size_t)r<<20)+(size_t)i*Sdim + j0 + u];
        }
        for(int idx=tid; idx<1024; idx+=256){
            int r=idx>>4, c=(idx&15)*4;
            float4 v=*(const float4*)&ev[(size_t)i*SD+(size_t)(j0+r)*Ddim+c];
            *(__half2*)&es[r*80+c]   = __floats2half2_rn(v.x,v.y);
            *(__half2*)&es[r*80+c+2] = __floats2half2_rn(v.z,v.w);
        }
        __syncthreads();
        #pragma unroll
        for(int kk=0;kk<4;kk++){
            FragAh a; wmma::load_matrix_sync(a, &ps[(wn*16)*80 + kk*16], 80);
            #pragma unroll
            for(int c=0;c<2;c++){
                FragBh b; wmma::load_matrix_sync(b, &es[(kk*16)*80 + wd*32 + c*16], 80);
                wmma::mma_sync(acc[c],a,b,acc[c]);
            }
        }
        __syncthreads();
    }
    #pragma unroll
    for(int c=0;c<2;c++)
        wmma::store_matrix_sync(&g_ctx[(size_t)i*(Bdim*Edim)+(size_t)(wn*16)*Ddim + wd*32 + c*16],
                                acc[c], Ddim, wmma::mem_row_major);
}

// =======================================================================
// K6: output projection + residual (tf32 TC) -> g_x
// =======================================================================
__global__ void __launch_bounds__(256) outproj_tc(const float* __restrict__ W,
    const float* __restrict__ bias, const float* __restrict__ resid)
{
    __shared__ float sx[128*72];
    int tid=threadIdx.x, w=tid>>5;
    int m0=blockIdx.x*128, o0=blockIdx.y*64;
    int wy=w&3, wx=w>>2;
    FragC acc[2][2];
    #pragma unroll
    for(int r=0;r<2;r++)
        #pragma unroll
        for(int c=0;c<2;c++) wmma::fill_fragment(acc[r][c],0.f);

    for(int k0=0;k0<Edim;k0+=8){
        FragA a[2]; FragBc b[2];
        #pragma unroll
        for(int r=0;r<2;r++){
            wmma::load_matrix_sync(a[r], g_ctx+(size_t)(m0+wy*32+r*16)*Edim+k0, Edim);
            cvt_tf32(a[r]);
        }
        #pragma unroll
        for(int c=0;c<2;c++){
            wmma::load_matrix_sync(b[c], W+(size_t)(o0+wx*32+c*16)*Edim+k0, Edim);
            cvt_tf32(b[c]);
        }
        #pragma unroll
        for(int r=0;r<2;r++)
            #pragma unroll
            for(int c=0;c<2;c++) wmma::mma_sync(acc[r][c],a[r],b[c],acc[r][c]);
    }
    #pragma unroll
    for(int r=0;r<2;r++)
        #pragma unroll
        for(int c=0;c<2;c++)
            wmma::store_matrix_sync(&sx[(wy*32+r*16)*72+wx*32+c*16],acc[r][c],72,wmma::mem_row_major);
    __syncthreads();

    int r=tid>>1, half=tid&1;
    int m=m0+r;
    size_t base=(size_t)m*Edim + o0 + half*32;
    #pragma unroll
    for(int u=0;u<8;u++){
        int d=half*32+u*4;
        float4 v=*(float4*)&sx[r*72+d];
        float4 rs=*(const float4*)&resid[base+u*4];
        v.x+=bias[o0+d]  +rs.x; v.y+=bias[o0+d+1]+rs.y;
        v.z+=bias[o0+d+2]+rs.z; v.w+=bias[o0+d+3]+rs.w;
        *(float4*)&g_x[base+u*4]=v;
    }
}

// =======================================================================
// K7: LayerNorm over last dim (512)
// =======================================================================
__global__ void __launch_bounds__(256) ln_kernel(const float* __restrict__ gamma,
     const float* __restrict__ beta, float* __restrict__ out)
{
    int m = blockIdx.x, tid = threadIdx.x;
    float a = g_x[(size_t)m*Edim + tid];
    float b = g_x[(size_t)m*Edim + 256 + tid];
    __shared__ float s1[256], s2[256];
    s1[tid] = a+b; s2[tid] = a*a + b*b;
    __syncthreads();
    for (int s=128;s>0;s>>=1){
        if(tid<s){ s1[tid]+=s1[tid+s]; s2[tid]+=s2[tid+s]; }
        __syncthreads();
    }
    float mean = s1[0] * (1.0f/512.0f);
    float var  = s2[0] * (1.0f/512.0f) - mean*mean;
    float rstd = rsqrtf(var + 1e-5f);
    out[(size_t)m*Edim + tid]       = gamma[tid]*(a-mean)*rstd + beta[tid];
    out[(size_t)m*Edim + 256 + tid] = gamma[256+tid]*(b-mean)*rstd + beta[256+tid];
}

// =======================================================================
extern "C" void kernel_launch(void* const* d_in, const int* in_sizes, int n_in,
                              void* d_out, int out_size)
{
    const float* query      = (const float*)d_in[0];
    const float* key        = (const float*)d_in[1];
    const float* value      = (const float*)d_in[2];
    const float* edge_key   = (const float*)d_in[3];
    const float* edge_value = (const float*)d_in[4];
    const int*   mask       = (const int*)  d_in[5];
    int base = (n_in == 17) ? 7 : 6;
    const float* Wq = (const float*)d_in[base+0];
    const float* bq = (const float*)d_in[base+1];
    const float* Wk = (const float*)d_in[base+2];
    const float* bk = (const float*)d_in[base+3];
    const float* Wv = (const float*)d_in[base+4];
    const float* bv = (const float*)d_in[base+5];
    const float* Wo = (const float*)d_in[base+6];
    const float* bo = (const float*)d_in[base+7];
    const float* gamma = (const float*)d_in[base+8];
    const float* beta  = (const float*)d_in[base+9];

    // smem: 576 f32 (q halfs) + 16*1032 f32 logits + 256*72 halfs (K chunk) = 105216 B
    const int ATTN_SMEM = (576 + 16*1032)*4 + 256*72*2;
    cudaFuncSetAttribute(attn_sm, cudaFuncAttributeMaxDynamicSharedMemorySize, ATTN_SMEM);

    proj_tc<<<dim3(64,8,3),256>>>(query,key,value, Wq,Wk,Wv, bq,bk,bv);
    biasgemm_tc<<<dim3(16,1024),256>>>(edge_key);
    bias_tr<<<dim3(16,1024),256>>>(mask);
    attn_sm<<<dim3(64,64),512,ATTN_SMEM>>>();
    pv_tc<<<dim3(8,64),256>>>();
    ev_tc<<<1024,256>>>(edge_value);
    outproj_tc<<<dim3(64,8),256>>>(Wo, bo, query);
    ln_kernel<<<dim3(8192),256>>>(gamma, beta, (float*)d_out);
}